// round 7
// baseline (speedup 1.0000x reference)
#include <cuda_runtime.h>
#include <cuda_bf16.h>
#include <math.h>

// Problem constants (fixed by setup_inputs)
#define NS 50000
#define NC 50000
#define D_DIM 128
#define H_DIM 512
#define LRELU 0.01f
#define LN_EPS 1e-5f

// ---------------- scratch (device globals; no allocs allowed) ----------------
__device__ float g_z[NS * D_DIM];       // z = s @ W_fc^T
__device__ float g_zs[NS];              // z @ a_attn[:D]
__device__ int   g_seg[NC + 1];         // segment starts in sorted dst_idx
__device__ float g_hc[NC * D_DIM];      // elu(h) + c
__device__ float g_t[NC * H_DIM];       // relu(hc @ w1^T + b1)
__device__ float g_y[NC * D_DIM];       // t @ w2^T + b2

// ---------------- tiled SGEMM: C[m,n] = act(sum_k A[m,k]*B[n,k] + bias[n]) ----------------
// BM=128, BN=64, BK=16, 256 threads, 8x4 register tile per thread.
// Double-buffered smem pipeline: one __syncthreads per k-tile, global loads
// for tile k+1 issued before compute on tile k. 2 CTAs/SM to hide barrier shadow.
// Requires: N % 64 == 0, K % 16 == 0 (true for all calls: N in {128,512}, K in {128,512}).
template <int ACT>
__global__ __launch_bounds__(256, 2)
void sgemm_bt_kernel(const float* __restrict__ A,
                     const float* __restrict__ B,
                     const float* __restrict__ bias,
                     float* __restrict__ C,
                     int M, int N, int K) {
    const int BM = 128, BN = 64, BK = 16;
    __shared__ float As[2][BK][BM];
    __shared__ float Bs[2][BK][BN];

    int tid = threadIdx.x;            // 0..255
    int tx = tid & 15;                // col group (cols tx*4 .. +3)
    int ty = tid >> 4;                // row group (rows ty*8 .. +7)
    int bm = blockIdx.y * BM;
    int bn = blockIdx.x * BN;

    // A loads: 2 float4 per thread. row = tid&127, k-offset = (tid>>7)*8 + {0,4}
    int a_row = tid & 127;
    int a_k0  = (tid >> 7) << 3;      // 0 or 8
    // B loads: 1 float4 per thread. row = tid&63, k-offset = (tid>>6)*4
    int b_row = tid & 63;
    int b_k0  = (tid >> 6) << 2;      // 0,4,8,12

    float acc[8][4];
#pragma unroll
    for (int i = 0; i < 8; i++)
#pragma unroll
        for (int j = 0; j < 4; j++) acc[i][j] = 0.f;

    int gm_a = bm + a_row;
    bool a_ok = (gm_a < M);
    const float* a_src = &A[(size_t)(a_ok ? gm_a : 0) * K];
    const float* b_src = &B[(size_t)(bn + b_row) * K];

    // ---- prologue: load tile 0 into buffer 0 ----
    {
        float4 av0 = make_float4(0.f, 0.f, 0.f, 0.f);
        float4 av1 = make_float4(0.f, 0.f, 0.f, 0.f);
        if (a_ok) {
            av0 = *reinterpret_cast<const float4*>(&a_src[a_k0 + 0]);
            av1 = *reinterpret_cast<const float4*>(&a_src[a_k0 + 4]);
        }
        float4 bv = *reinterpret_cast<const float4*>(&b_src[b_k0]);
        As[0][a_k0 + 0][a_row] = av0.x;
        As[0][a_k0 + 1][a_row] = av0.y;
        As[0][a_k0 + 2][a_row] = av0.z;
        As[0][a_k0 + 3][a_row] = av0.w;
        As[0][a_k0 + 4][a_row] = av1.x;
        As[0][a_k0 + 5][a_row] = av1.y;
        As[0][a_k0 + 6][a_row] = av1.z;
        As[0][a_k0 + 7][a_row] = av1.w;
        Bs[0][b_k0 + 0][b_row] = bv.x;
        Bs[0][b_k0 + 1][b_row] = bv.y;
        Bs[0][b_k0 + 2][b_row] = bv.z;
        Bs[0][b_k0 + 3][b_row] = bv.w;
    }
    __syncthreads();

    int buf = 0;
    for (int k0 = 0; k0 < K; k0 += BK) {
        int knext = k0 + BK;
        bool have_next = (knext < K);

        // ---- issue global loads for tile k+1 (in flight during compute) ----
        float4 av0, av1, bv;
        if (have_next) {
            av0 = make_float4(0.f, 0.f, 0.f, 0.f);
            av1 = make_float4(0.f, 0.f, 0.f, 0.f);
            if (a_ok) {
                av0 = *reinterpret_cast<const float4*>(&a_src[knext + a_k0 + 0]);
                av1 = *reinterpret_cast<const float4*>(&a_src[knext + a_k0 + 4]);
            }
            bv = *reinterpret_cast<const float4*>(&b_src[knext + b_k0]);
        }

        // ---- compute on buffer `buf` ----
#pragma unroll
        for (int kk = 0; kk < BK; kk++) {
            float4 a0 = *reinterpret_cast<const float4*>(&As[buf][kk][ty << 3]);
            float4 a1 = *reinterpret_cast<const float4*>(&As[buf][kk][(ty << 3) + 4]);
            float4 b4 = *reinterpret_cast<const float4*>(&Bs[buf][kk][tx << 2]);
            float ar[8] = {a0.x, a0.y, a0.z, a0.w, a1.x, a1.y, a1.z, a1.w};
            float br[4] = {b4.x, b4.y, b4.z, b4.w};
#pragma unroll
            for (int i = 0; i < 8; i++)
#pragma unroll
                for (int j = 0; j < 4; j++) acc[i][j] += ar[i] * br[j];
        }

        // ---- store prefetched tile into the other buffer ----
        if (have_next) {
            int nb = buf ^ 1;
            As[nb][a_k0 + 0][a_row] = av0.x;
            As[nb][a_k0 + 1][a_row] = av0.y;
            As[nb][a_k0 + 2][a_row] = av0.z;
            As[nb][a_k0 + 3][a_row] = av0.w;
            As[nb][a_k0 + 4][a_row] = av1.x;
            As[nb][a_k0 + 5][a_row] = av1.y;
            As[nb][a_k0 + 6][a_row] = av1.z;
            As[nb][a_k0 + 7][a_row] = av1.w;
            Bs[nb][b_k0 + 0][b_row] = bv.x;
            Bs[nb][b_k0 + 1][b_row] = bv.y;
            Bs[nb][b_k0 + 2][b_row] = bv.z;
            Bs[nb][b_k0 + 3][b_row] = bv.w;
            __syncthreads();
            buf = nb;
        }
    }

    // epilogue: bias + activation, vectorized float4 store
    int n0 = bn + (tx << 2);
    float4 bi = make_float4(0.f, 0.f, 0.f, 0.f);
    if (bias) bi = *reinterpret_cast<const float4*>(&bias[n0]);
#pragma unroll
    for (int i = 0; i < 8; i++) {
        int m = bm + (ty << 3) + i;
        if (m >= M) continue;
        float4 v;
        v.x = acc[i][0] + bi.x;
        v.y = acc[i][1] + bi.y;
        v.z = acc[i][2] + bi.z;
        v.w = acc[i][3] + bi.w;
        if (ACT == 1) {  // relu
            v.x = fmaxf(v.x, 0.f); v.y = fmaxf(v.y, 0.f);
            v.z = fmaxf(v.z, 0.f); v.w = fmaxf(v.w, 0.f);
        }
        *reinterpret_cast<float4*>(&C[(size_t)m * N + n0]) = v;
    }
}

// ---------------- zs[i] = dot(z[i,:], a[:128]) : one warp per row ----------------
__global__ void zs_kernel(const float* __restrict__ z,
                          const float* __restrict__ a,
                          float* __restrict__ zs, int Ns) {
    int warp = (blockIdx.x * blockDim.x + threadIdx.x) >> 5;
    int lane = threadIdx.x & 31;
    if (warp >= Ns) return;
    float4 zv = *reinterpret_cast<const float4*>(&z[(size_t)warp * D_DIM + (lane << 2)]);
    float4 av = *reinterpret_cast<const float4*>(&a[lane << 2]);
    float s = zv.x * av.x + zv.y * av.y + zv.z * av.z + zv.w * av.w;
#pragma unroll
    for (int o = 16; o; o >>= 1) s += __shfl_xor_sync(0xFFFFFFFFu, s, o);
    if (lane == 0) zs[warp] = s;
}

// ---------------- segment starts from sorted dst_idx ----------------
__global__ void segstart_kernel(const int* __restrict__ dst, int* __restrict__ seg,
                                int E, int Nc) {
    int i = blockIdx.x * blockDim.x + threadIdx.x;
    if (i >= E) return;
    int dcur = dst[i];
    int dprev = (i == 0) ? -1 : dst[i - 1];
    for (int d = dprev + 1; d <= dcur; ++d) seg[d] = i;
    if (i == E - 1) {
        for (int d = dcur + 1; d <= Nc; ++d) seg[d] = E;
    }
}

// ---------------- fused segment softmax + aggregation + elu + residual c ----------------
// one warp per dst node; pass-2 unrolled x4 for MLP
__global__ void agg_kernel(const float* __restrict__ z,
                           const float* __restrict__ zs,
                           const int* __restrict__ src_idx,
                           const int* __restrict__ seg,
                           const float* __restrict__ c,
                           float* __restrict__ hc, int Nc) {
    int warp = (blockIdx.x * blockDim.x + threadIdx.x) >> 5;
    int lane = threadIdx.x & 31;
    if (warp >= Nc) return;
    int s0 = seg[warp];
    int s1 = seg[warp + 1];
    float4 cv = *reinterpret_cast<const float4*>(&c[(size_t)warp * D_DIM + (lane << 2)]);
    float4 out;
    if (s0 == s1) {
        out = cv;  // no in-edges: h = 0, elu(0) = 0
    } else {
        // pass 1: segment max of leaky_relu(zs[src])
        float m = -INFINITY;
        for (int e = s0 + lane; e < s1; e += 32) {
            float x = zs[src_idx[e]];
            x = x > 0.f ? x : LRELU * x;
            m = fmaxf(m, x);
        }
#pragma unroll
        for (int o = 16; o; o >>= 1) m = fmaxf(m, __shfl_xor_sync(0xFFFFFFFFu, m, o));
        // pass 2: denom = sum exp(e-m); acc = sum exp(e-m) * z[src]
        // 4-way unrolled: four independent L2 gathers in flight per iteration.
        float denom = 0.f;
        float4 acc = make_float4(0.f, 0.f, 0.f, 0.f);
        int e = s0;
        for (; e + 4 <= s1; e += 4) {
            int si0 = src_idx[e];
            int si1 = src_idx[e + 1];
            int si2 = src_idx[e + 2];
            int si3 = src_idx[e + 3];
            float x0 = zs[si0];
            float x1 = zs[si1];
            float x2 = zs[si2];
            float x3 = zs[si3];
            float4 zv0 = *reinterpret_cast<const float4*>(&z[(size_t)si0 * D_DIM + (lane << 2)]);
            float4 zv1 = *reinterpret_cast<const float4*>(&z[(size_t)si1 * D_DIM + (lane << 2)]);
            float4 zv2 = *reinterpret_cast<const float4*>(&z[(size_t)si2 * D_DIM + (lane << 2)]);
            float4 zv3 = *reinterpret_cast<const float4*>(&z[(size_t)si3 * D_DIM + (lane << 2)]);
            x0 = x0 > 0.f ? x0 : LRELU * x0;
            x1 = x1 > 0.f ? x1 : LRELU * x1;
            x2 = x2 > 0.f ? x2 : LRELU * x2;
            x3 = x3 > 0.f ? x3 : LRELU * x3;
            float w0 = __expf(x0 - m);
            float w1 = __expf(x1 - m);
            float w2 = __expf(x2 - m);
            float w3 = __expf(x3 - m);
            denom += (w0 + w1) + (w2 + w3);
            acc.x += w0 * zv0.x + w1 * zv1.x + w2 * zv2.x + w3 * zv3.x;
            acc.y += w0 * zv0.y + w1 * zv1.y + w2 * zv2.y + w3 * zv3.y;
            acc.z += w0 * zv0.z + w1 * zv1.z + w2 * zv2.z + w3 * zv3.z;
            acc.w += w0 * zv0.w + w1 * zv1.w + w2 * zv2.w + w3 * zv3.w;
        }
        for (; e < s1; ++e) {
            int si = src_idx[e];
            float x = zs[si];
            x = x > 0.f ? x : LRELU * x;
            float w = __expf(x - m);
            float4 zv = *reinterpret_cast<const float4*>(&z[(size_t)si * D_DIM + (lane << 2)]);
            denom += w;
            acc.x += w * zv.x; acc.y += w * zv.y;
            acc.z += w * zv.z; acc.w += w * zv.w;
        }
        float inv = 1.f / denom;
        float hx = acc.x * inv, hy = acc.y * inv, hz = acc.z * inv, hw = acc.w * inv;
        out.x = (hx > 0.f ? hx : expm1f(hx)) + cv.x;
        out.y = (hy > 0.f ? hy : expm1f(hy)) + cv.y;
        out.z = (hz > 0.f ? hz : expm1f(hz)) + cv.z;
        out.w = (hw > 0.f ? hw : expm1f(hw)) + cv.w;
    }
    *reinterpret_cast<float4*>(&hc[(size_t)warp * D_DIM + (lane << 2)]) = out;
}

// ---------------- residual + layernorm: out = LN(y + hc) * g + b ----------------
// one warp per row
__global__ void ln_kernel(const float* __restrict__ y,
                          const float* __restrict__ hc,
                          const float* __restrict__ gamma,
                          const float* __restrict__ beta,
                          float* __restrict__ out, int Nc) {
    int warp = (blockIdx.x * blockDim.x + threadIdx.x) >> 5;
    int lane = threadIdx.x & 31;
    if (warp >= Nc) return;
    size_t base = (size_t)warp * D_DIM + (lane << 2);
    float4 yv = *reinterpret_cast<const float4*>(&y[base]);
    float4 hv = *reinterpret_cast<const float4*>(&hc[base]);
    float v0 = yv.x + hv.x, v1 = yv.y + hv.y, v2 = yv.z + hv.z, v3 = yv.w + hv.w;
    float s = v0 + v1 + v2 + v3;
#pragma unroll
    for (int o = 16; o; o >>= 1) s += __shfl_xor_sync(0xFFFFFFFFu, s, o);
    float mu = s * (1.0f / D_DIM);
    float d0 = v0 - mu, d1 = v1 - mu, d2 = v2 - mu, d3 = v3 - mu;
    float q = d0 * d0 + d1 * d1 + d2 * d2 + d3 * d3;
#pragma unroll
    for (int o = 16; o; o >>= 1) q += __shfl_xor_sync(0xFFFFFFFFu, q, o);
    float rs = rsqrtf(q * (1.0f / D_DIM) + LN_EPS);
    float4 gv = *reinterpret_cast<const float4*>(&gamma[lane << 2]);
    float4 bv = *reinterpret_cast<const float4*>(&beta[lane << 2]);
    float4 o4;
    o4.x = d0 * rs * gv.x + bv.x;
    o4.y = d1 * rs * gv.y + bv.y;
    o4.z = d2 * rs * gv.z + bv.z;
    o4.w = d3 * rs * gv.w + bv.w;
    *reinterpret_cast<float4*>(&out[base]) = o4;
}

// ---------------- launch ----------------
extern "C" void kernel_launch(void* const* d_in, const int* in_sizes, int n_in,
                              void* d_out, int out_size) {
    const float* s       = (const float*)d_in[0];
    const float* c       = (const float*)d_in[1];
    const int*   src_idx = (const int*)d_in[2];
    const int*   dst_idx = (const int*)d_in[3];
    const float* W_fc    = (const float*)d_in[4];
    const float* a_attn  = (const float*)d_in[5];
    const float* w1      = (const float*)d_in[6];
    const float* b1      = (const float*)d_in[7];
    const float* w2      = (const float*)d_in[8];
    const float* b2      = (const float*)d_in[9];
    const float* ln_g    = (const float*)d_in[10];
    const float* ln_b    = (const float*)d_in[11];
    float* out = (float*)d_out;

    int Ns = in_sizes[0] / D_DIM;
    int Nc = in_sizes[1] / D_DIM;
    int E  = in_sizes[2];

    float* z  = nullptr; cudaGetSymbolAddress((void**)&z,  g_z);
    float* zs = nullptr; cudaGetSymbolAddress((void**)&zs, g_zs);
    int*   sg = nullptr; cudaGetSymbolAddress((void**)&sg, g_seg);
    float* hc = nullptr; cudaGetSymbolAddress((void**)&hc, g_hc);
    float* t  = nullptr; cudaGetSymbolAddress((void**)&t,  g_t);
    float* y  = nullptr; cudaGetSymbolAddress((void**)&y,  g_y);

    // 1) z = s @ W_fc^T   [Ns,128]
    {
        dim3 grid(D_DIM / 64, (Ns + 127) / 128);
        sgemm_bt_kernel<0><<<grid, 256>>>(s, W_fc, nullptr, z, Ns, D_DIM, D_DIM);
    }
    // 2) zs = z @ a_attn[:128]
    zs_kernel<<<(Ns * 32 + 255) / 256, 256>>>(z, a_attn, zs, Ns);
    // 3) segment starts from sorted dst
    segstart_kernel<<<(E + 255) / 256, 256>>>(dst_idx, sg, E, Nc);
    // 4) fused segment softmax + aggregate + elu + residual
    agg_kernel<<<(Nc * 32 + 255) / 256, 256>>>(z, zs, src_idx, sg, c, hc, Nc);
    // 5) t = relu(hc @ w1^T + b1)   [Nc,512]
    {
        dim3 grid(H_DIM / 64, (Nc + 127) / 128);
        sgemm_bt_kernel<1><<<grid, 256>>>(hc, w1, b1, t, Nc, H_DIM, D_DIM);
    }
    // 6) y = t @ w2^T + b2          [Nc,128]
    {
        dim3 grid(D_DIM / 64, (Nc + 127) / 128);
        sgemm_bt_kernel<0><<<grid, 256>>>(t, w2, b2, y, Nc, D_DIM, H_DIM);
    }
    // 7) out = LN(y + hc)
    ln_kernel<<<(Nc * 32 + 255) / 256, 256>>>(y, hc, ln_g, ln_b, out, Nc);
}

// round 14
// speedup vs baseline: 1.7992x; 1.7992x over previous
#include <cuda_runtime.h>
#include <cuda_bf16.h>
#include <math.h>
#include <stdint.h>

#define NS 50000
#define NC 50000
#define D_DIM 128
#define H_DIM 512
#define LRELU 0.01f
#define LN_EPS 1e-5f

// ---------------- scratch (device globals; no allocs allowed) ----------------
__device__ float g_z[NS * D_DIM];
__device__ float g_zs[NS];
__device__ int   g_seg[NC + 1];
__device__ float g_hc[NC * D_DIM];
__device__ float g_y[NC * D_DIM];
// split-bf16 operands
__device__ __nv_bfloat16 g_s_h[NS * D_DIM],  g_s_l[NS * D_DIM];
__device__ __nv_bfloat16 g_hc_h[NC * D_DIM], g_hc_l[NC * D_DIM];
__device__ __nv_bfloat16 g_t_h[NC * H_DIM],  g_t_l[NC * H_DIM];
__device__ __nv_bfloat16 g_wfc_h[D_DIM * D_DIM], g_wfc_l[D_DIM * D_DIM];
__device__ __nv_bfloat16 g_w1_h[H_DIM * D_DIM],  g_w1_l[H_DIM * D_DIM];
__device__ __nv_bfloat16 g_w2_h[D_DIM * H_DIM],  g_w2_l[D_DIM * H_DIM];

// ---------------- warp-level MMA helpers (sm_80-level; safe on base sm_103 target) ----------
__device__ __forceinline__ void ldm_x4(uint32_t& r0, uint32_t& r1, uint32_t& r2, uint32_t& r3,
                                       uint32_t addr) {
    asm volatile("ldmatrix.sync.aligned.m8n8.x4.shared.b16 {%0,%1,%2,%3}, [%4];"
                 : "=r"(r0), "=r"(r1), "=r"(r2), "=r"(r3) : "r"(addr));
}
__device__ __forceinline__ void mma_bf16(float* d, const uint32_t* a, const uint32_t* b) {
    asm volatile(
        "mma.sync.aligned.m16n8k16.row.col.f32.bf16.bf16.f32 "
        "{%0,%1,%2,%3}, {%4,%5,%6,%7}, {%8,%9}, {%0,%1,%2,%3};"
        : "+f"(d[0]), "+f"(d[1]), "+f"(d[2]), "+f"(d[3])
        : "r"(a[0]), "r"(a[1]), "r"(a[2]), "r"(a[3]), "r"(b[0]), "r"(b[1]));
}

// ---------------- split fp32 -> (bf16 hi, bf16 lo) ----------------
__global__ void split_kernel(const float* __restrict__ x,
                             __nv_bfloat16* __restrict__ h,
                             __nv_bfloat16* __restrict__ l, int n) {
    int i = blockIdx.x * blockDim.x + threadIdx.x;
    if (i >= n) return;
    float v = x[i];
    __nv_bfloat16 hv = __float2bfloat16(v);
    h[i] = hv;
    l[i] = __float2bfloat16(v - __bfloat162float(hv));
}

// ---------------- split-bf16 HMMA GEMM: C[m,n] = epi(sum_k A[m,k]*B[n,k]) ----------------
// BM=128, BN=64, BK=32. 256 threads = 8 warps in 4(m) x 2(n); warp tile 32x32.
// 3-product split: acc += Ah*Bh + Ah*Bl + Al*Bh  (fp32 accumulate).
// smem rows padded to 40 bf16 (80B) -> conflict-free ldmatrix.
// OUT: 0 = fp32 store, 1 = relu(v+bias) -> split bf16 (Ch,Cl), 2 = v+bias fp32.
#define PAD 40
#define A_T_ELEMS (128 * PAD)      // 5120
#define B_T_ELEMS (64 * PAD)       // 2560
#define OFF_AH 0
#define OFF_AL A_T_ELEMS
#define OFF_BH (2 * A_T_ELEMS)
#define OFF_BL (2 * A_T_ELEMS + B_T_ELEMS)
#define BUF_ELEMS (2 * A_T_ELEMS + 2 * B_T_ELEMS)          // 15360 elems
#define MM_SMEM_BYTES (2 * BUF_ELEMS * 2)                  // 61440 bytes

template <int OUT>
__global__ __launch_bounds__(256, 2)
void mma_gemm(const __nv_bfloat16* __restrict__ Ahg, const __nv_bfloat16* __restrict__ Alg,
              const __nv_bfloat16* __restrict__ Bhg, const __nv_bfloat16* __restrict__ Blg,
              const float* __restrict__ bias,
              float* __restrict__ Cf,
              __nv_bfloat16* __restrict__ Ch, __nv_bfloat16* __restrict__ Cl,
              int M, int N, int K) {
    extern __shared__ __nv_bfloat16 smem[];
    uint32_t smem_u32 = (uint32_t)__cvta_generic_to_shared(smem);

    int tid  = threadIdx.x;
    int lane = tid & 31;
    int wid  = tid >> 5;
    int wm   = wid & 3;            // warp m-tile (0..3) -> rows wm*32..+31
    int wn   = wid >> 2;           // warp n-tile (0..1) -> cols wn*32..+31
    int bm = blockIdx.y * 128;
    int bn = blockIdx.x * 64;

    // ---- load/store mapping for tiles (uint4 = 8 bf16 chunks) ----
    int a_r0 = tid >> 2;           // 0..63
    int a_c  = (tid & 3) * 8;      // element col offset
    int a_r1 = a_r0 + 64;
    int b_r = tid >> 2;
    int b_c = (tid & 3) * 8;
    bool okA0 = (bm + a_r0) < M;
    bool okA1 = (bm + a_r1) < M;
    const __nv_bfloat16* a0h = &Ahg[(size_t)(okA0 ? bm + a_r0 : 0) * K + a_c];
    const __nv_bfloat16* a1h = &Ahg[(size_t)(okA1 ? bm + a_r1 : 0) * K + a_c];
    const __nv_bfloat16* a0l = &Alg[(size_t)(okA0 ? bm + a_r0 : 0) * K + a_c];
    const __nv_bfloat16* a1l = &Alg[(size_t)(okA1 ? bm + a_r1 : 0) * K + a_c];
    const __nv_bfloat16* bgh = &Bhg[(size_t)(bn + b_r) * K + b_c];
    const __nv_bfloat16* bgl = &Blg[(size_t)(bn + b_r) * K + b_c];

    // ldmatrix per-lane offsets
    int aRow = lane & 15;
    int aCol = (lane >> 4) << 3;
    int bRow = ((lane >> 4) << 3) + (lane & 7);
    int bCol = ((lane >> 3) & 1) << 3;

    float acc[2][4][4];
#pragma unroll
    for (int i = 0; i < 2; i++)
#pragma unroll
        for (int j = 0; j < 4; j++)
#pragma unroll
            for (int q = 0; q < 4; q++) acc[i][j][q] = 0.f;

    const uint4 zero4 = make_uint4(0u, 0u, 0u, 0u);

    // ---- prologue: fill buffer 0 with k-block 0 ----
    {
        uint4 v;
        v = okA0 ? *reinterpret_cast<const uint4*>(a0h) : zero4;
        *reinterpret_cast<uint4*>(&smem[OFF_AH + a_r0 * PAD + a_c]) = v;
        v = okA1 ? *reinterpret_cast<const uint4*>(a1h) : zero4;
        *reinterpret_cast<uint4*>(&smem[OFF_AH + a_r1 * PAD + a_c]) = v;
        v = okA0 ? *reinterpret_cast<const uint4*>(a0l) : zero4;
        *reinterpret_cast<uint4*>(&smem[OFF_AL + a_r0 * PAD + a_c]) = v;
        v = okA1 ? *reinterpret_cast<const uint4*>(a1l) : zero4;
        *reinterpret_cast<uint4*>(&smem[OFF_AL + a_r1 * PAD + a_c]) = v;
        *reinterpret_cast<uint4*>(&smem[OFF_BH + b_r * PAD + b_c]) =
            *reinterpret_cast<const uint4*>(bgh);
        *reinterpret_cast<uint4*>(&smem[OFF_BL + b_r * PAD + b_c]) =
            *reinterpret_cast<const uint4*>(bgl);
    }
    __syncthreads();

    int nkb = K >> 5;              // k-blocks of 32
    for (int kb = 0; kb < nkb; kb++) {
        int bufOff = (kb & 1) * BUF_ELEMS;
        bool have_next = (kb + 1 < nkb);

        // prefetch next k-block into registers
        uint4 p0, p1, p2, p3, p4, p5;
        if (have_next) {
            int kc = (kb + 1) << 5;
            p0 = okA0 ? *reinterpret_cast<const uint4*>(a0h + kc) : zero4;
            p1 = okA1 ? *reinterpret_cast<const uint4*>(a1h + kc) : zero4;
            p2 = okA0 ? *reinterpret_cast<const uint4*>(a0l + kc) : zero4;
            p3 = okA1 ? *reinterpret_cast<const uint4*>(a1l + kc) : zero4;
            p4 = *reinterpret_cast<const uint4*>(bgh + kc);
            p5 = *reinterpret_cast<const uint4*>(bgl + kc);
        }

        // compute current buffer: 2 x k16 steps
#pragma unroll
        for (int ks = 0; ks < 2; ks++) {
            int kcol = ks * 16;
            uint32_t aH[2][4], aL[2][4], bH[4][2], bL[4][2];
#pragma unroll
            for (int mi = 0; mi < 2; mi++) {
                uint32_t ad = smem_u32 + 2u * (uint32_t)(bufOff + OFF_AH +
                              (wm * 32 + mi * 16 + aRow) * PAD + kcol + aCol);
                ldm_x4(aH[mi][0], aH[mi][1], aH[mi][2], aH[mi][3], ad);
                uint32_t al = smem_u32 + 2u * (uint32_t)(bufOff + OFF_AL +
                              (wm * 32 + mi * 16 + aRow) * PAD + kcol + aCol);
                ldm_x4(aL[mi][0], aL[mi][1], aL[mi][2], aL[mi][3], al);
            }
#pragma unroll
            for (int nj = 0; nj < 2; nj++) {
                uint32_t bd = smem_u32 + 2u * (uint32_t)(bufOff + OFF_BH +
                              (wn * 32 + nj * 16 + bRow) * PAD + kcol + bCol);
                ldm_x4(bH[2 * nj][0], bH[2 * nj][1], bH[2 * nj + 1][0], bH[2 * nj + 1][1], bd);
                uint32_t bl = smem_u32 + 2u * (uint32_t)(bufOff + OFF_BL +
                              (wn * 32 + nj * 16 + bRow) * PAD + kcol + bCol);
                ldm_x4(bL[2 * nj][0], bL[2 * nj][1], bL[2 * nj + 1][0], bL[2 * nj + 1][1], bl);
            }
#pragma unroll
            for (int mi = 0; mi < 2; mi++)
#pragma unroll
                for (int ni = 0; ni < 4; ni++) {
                    mma_bf16(acc[mi][ni], aH[mi], bH[ni]);
                    mma_bf16(acc[mi][ni], aH[mi], bL[ni]);
                    mma_bf16(acc[mi][ni], aL[mi], bH[ni]);
                }
        }

        // store prefetched tiles into other buffer
        if (have_next) {
            int nb = ((kb + 1) & 1) * BUF_ELEMS;
            *reinterpret_cast<uint4*>(&smem[nb + OFF_AH + a_r0 * PAD + a_c]) = p0;
            *reinterpret_cast<uint4*>(&smem[nb + OFF_AH + a_r1 * PAD + a_c]) = p1;
            *reinterpret_cast<uint4*>(&smem[nb + OFF_AL + a_r0 * PAD + a_c]) = p2;
            *reinterpret_cast<uint4*>(&smem[nb + OFF_AL + a_r1 * PAD + a_c]) = p3;
            *reinterpret_cast<uint4*>(&smem[nb + OFF_BH + b_r * PAD + b_c]) = p4;
            *reinterpret_cast<uint4*>(&smem[nb + OFF_BL + b_r * PAD + b_c]) = p5;
            __syncthreads();
        }
    }

    // ---- epilogue: fragment layout m16n8 -> direct global stores ----
    int tg = lane >> 2;            // 0..7
    int tc = (lane & 3) << 1;      // 0,2,4,6
#pragma unroll
    for (int mi = 0; mi < 2; mi++) {
#pragma unroll
        for (int ni = 0; ni < 4; ni++) {
            int gm0 = bm + wm * 32 + mi * 16 + tg;
            int gm1 = gm0 + 8;
            int gn  = bn + wn * 32 + ni * 8 + tc;
            float2 bv = make_float2(0.f, 0.f);
            if (OUT != 0) bv = *reinterpret_cast<const float2*>(&bias[gn]);
            float v00 = acc[mi][ni][0], v01 = acc[mi][ni][1];
            float v10 = acc[mi][ni][2], v11 = acc[mi][ni][3];
            if (OUT == 0) {
                if (gm0 < M) *reinterpret_cast<float2*>(&Cf[(size_t)gm0 * N + gn]) = make_float2(v00, v01);
                if (gm1 < M) *reinterpret_cast<float2*>(&Cf[(size_t)gm1 * N + gn]) = make_float2(v10, v11);
            } else if (OUT == 2) {
                if (gm0 < M) *reinterpret_cast<float2*>(&Cf[(size_t)gm0 * N + gn]) =
                    make_float2(v00 + bv.x, v01 + bv.y);
                if (gm1 < M) *reinterpret_cast<float2*>(&Cf[(size_t)gm1 * N + gn]) =
                    make_float2(v10 + bv.x, v11 + bv.y);
            } else {
                v00 = fmaxf(v00 + bv.x, 0.f); v01 = fmaxf(v01 + bv.y, 0.f);
                v10 = fmaxf(v10 + bv.x, 0.f); v11 = fmaxf(v11 + bv.y, 0.f);
                if (gm0 < M) {
                    __nv_bfloat16 h0 = __float2bfloat16(v00), h1 = __float2bfloat16(v01);
                    *reinterpret_cast<__nv_bfloat162*>(&Ch[(size_t)gm0 * N + gn]) =
                        __halves2bfloat162(h0, h1);
                    *reinterpret_cast<__nv_bfloat162*>(&Cl[(size_t)gm0 * N + gn]) =
                        __halves2bfloat162(__float2bfloat16(v00 - __bfloat162float(h0)),
                                           __float2bfloat16(v01 - __bfloat162float(h1)));
                }
                if (gm1 < M) {
                    __nv_bfloat16 h0 = __float2bfloat16(v10), h1 = __float2bfloat16(v11);
                    *reinterpret_cast<__nv_bfloat162*>(&Ch[(size_t)gm1 * N + gn]) =
                        __halves2bfloat162(h0, h1);
                    *reinterpret_cast<__nv_bfloat162*>(&Cl[(size_t)gm1 * N + gn]) =
                        __halves2bfloat162(__float2bfloat16(v10 - __bfloat162float(h0)),
                                           __float2bfloat16(v11 - __bfloat162float(h1)));
                }
            }
        }
    }
}

// ---------------- zs[i] = dot(z[i,:], a[:128]) ----------------
__global__ void zs_kernel(const float* __restrict__ z, const float* __restrict__ a,
                          float* __restrict__ zs, int Ns) {
    int warp = (blockIdx.x * blockDim.x + threadIdx.x) >> 5;
    int lane = threadIdx.x & 31;
    if (warp >= Ns) return;
    float4 zv = *reinterpret_cast<const float4*>(&z[(size_t)warp * D_DIM + (lane << 2)]);
    float4 av = *reinterpret_cast<const float4*>(&a[lane << 2]);
    float s = zv.x * av.x + zv.y * av.y + zv.z * av.z + zv.w * av.w;
#pragma unroll
    for (int o = 16; o; o >>= 1) s += __shfl_xor_sync(0xFFFFFFFFu, s, o);
    if (lane == 0) zs[warp] = s;
}

// ---------------- segment starts from sorted dst_idx ----------------
__global__ void segstart_kernel(const int* __restrict__ dst, int* __restrict__ seg,
                                int E, int Nc) {
    int i = blockIdx.x * blockDim.x + threadIdx.x;
    if (i >= E) return;
    int dcur = dst[i];
    int dprev = (i == 0) ? -1 : dst[i - 1];
    for (int d = dprev + 1; d <= dcur; ++d) seg[d] = i;
    if (i == E - 1)
        for (int d = dcur + 1; d <= Nc; ++d) seg[d] = E;
}

// ---------------- fused segment softmax + aggregation + elu + residual ----------------
__global__ void agg_kernel(const float* __restrict__ z, const float* __restrict__ zs,
                           const int* __restrict__ src_idx, const int* __restrict__ seg,
                           const float* __restrict__ c, float* __restrict__ hc,
                           __nv_bfloat16* __restrict__ hch, __nv_bfloat16* __restrict__ hcl,
                           int Nc) {
    int warp = (blockIdx.x * blockDim.x + threadIdx.x) >> 5;
    int lane = threadIdx.x & 31;
    if (warp >= Nc) return;
    int s0 = seg[warp];
    int s1 = seg[warp + 1];
    float4 cv = *reinterpret_cast<const float4*>(&c[(size_t)warp * D_DIM + (lane << 2)]);
    float4 out;
    if (s0 == s1) {
        out = cv;
    } else {
        float m = -INFINITY;
        for (int e = s0 + lane; e < s1; e += 32) {
            float x = zs[src_idx[e]];
            x = x > 0.f ? x : LRELU * x;
            m = fmaxf(m, x);
        }
#pragma unroll
        for (int o = 16; o; o >>= 1) m = fmaxf(m, __shfl_xor_sync(0xFFFFFFFFu, m, o));
        float denom = 0.f;
        float4 acc = make_float4(0.f, 0.f, 0.f, 0.f);
        int e = s0;
        for (; e + 4 <= s1; e += 4) {
            int si0 = src_idx[e], si1 = src_idx[e + 1], si2 = src_idx[e + 2], si3 = src_idx[e + 3];
            float x0 = zs[si0], x1 = zs[si1], x2 = zs[si2], x3 = zs[si3];
            float4 zv0 = *reinterpret_cast<const float4*>(&z[(size_t)si0 * D_DIM + (lane << 2)]);
            float4 zv1 = *reinterpret_cast<const float4*>(&z[(size_t)si1 * D_DIM + (lane << 2)]);
            float4 zv2 = *reinterpret_cast<const float4*>(&z[(size_t)si2 * D_DIM + (lane << 2)]);
            float4 zv3 = *reinterpret_cast<const float4*>(&z[(size_t)si3 * D_DIM + (lane << 2)]);
            x0 = x0 > 0.f ? x0 : LRELU * x0; x1 = x1 > 0.f ? x1 : LRELU * x1;
            x2 = x2 > 0.f ? x2 : LRELU * x2; x3 = x3 > 0.f ? x3 : LRELU * x3;
            float w0 = __expf(x0 - m), w1 = __expf(x1 - m), w2 = __expf(x2 - m), w3 = __expf(x3 - m);
            denom += (w0 + w1) + (w2 + w3);
            acc.x += w0 * zv0.x + w1 * zv1.x + w2 * zv2.x + w3 * zv3.x;
            acc.y += w0 * zv0.y + w1 * zv1.y + w2 * zv2.y + w3 * zv3.y;
            acc.z += w0 * zv0.z + w1 * zv1.z + w2 * zv2.z + w3 * zv3.z;
            acc.w += w0 * zv0.w + w1 * zv1.w + w2 * zv2.w + w3 * zv3.w;
        }
        for (; e < s1; ++e) {
            int si = src_idx[e];
            float x = zs[si];
            x = x > 0.f ? x : LRELU * x;
            float w = __expf(x - m);
            float4 zv = *reinterpret_cast<const float4*>(&z[(size_t)si * D_DIM + (lane << 2)]);
            denom += w;
            acc.x += w * zv.x; acc.y += w * zv.y; acc.z += w * zv.z; acc.w += w * zv.w;
        }
        float inv = 1.f / denom;
        float hx = acc.x * inv, hy = acc.y * inv, hz = acc.z * inv, hw = acc.w * inv;
        out.x = (hx > 0.f ? hx : expm1f(hx)) + cv.x;
        out.y = (hy > 0.f ? hy : expm1f(hy)) + cv.y;
        out.z = (hz > 0.f ? hz : expm1f(hz)) + cv.z;
        out.w = (hw > 0.f ? hw : expm1f(hw)) + cv.w;
    }
    size_t base = (size_t)warp * D_DIM + (lane << 2);
    *reinterpret_cast<float4*>(&hc[base]) = out;
    __nv_bfloat16 h0 = __float2bfloat16(out.x), h1 = __float2bfloat16(out.y);
    __nv_bfloat16 h2 = __float2bfloat16(out.z), h3 = __float2bfloat16(out.w);
    *reinterpret_cast<__nv_bfloat162*>(&hch[base])     = __halves2bfloat162(h0, h1);
    *reinterpret_cast<__nv_bfloat162*>(&hch[base + 2]) = __halves2bfloat162(h2, h3);
    *reinterpret_cast<__nv_bfloat162*>(&hcl[base]) =
        __halves2bfloat162(__float2bfloat16(out.x - __bfloat162float(h0)),
                           __float2bfloat16(out.y - __bfloat162float(h1)));
    *reinterpret_cast<__nv_bfloat162*>(&hcl[base + 2]) =
        __halves2bfloat162(__float2bfloat16(out.z - __bfloat162float(h2)),
                           __float2bfloat16(out.w - __bfloat162float(h3)));
}

// ---------------- residual + layernorm ----------------
__global__ void ln_kernel(const float* __restrict__ y, const float* __restrict__ hc,
                          const float* __restrict__ gamma, const float* __restrict__ beta,
                          float* __restrict__ out, int Nc) {
    int warp = (blockIdx.x * blockDim.x + threadIdx.x) >> 5;
    int lane = threadIdx.x & 31;
    if (warp >= Nc) return;
    size_t base = (size_t)warp * D_DIM + (lane << 2);
    float4 yv = *reinterpret_cast<const float4*>(&y[base]);
    float4 hv = *reinterpret_cast<const float4*>(&hc[base]);
    float v0 = yv.x + hv.x, v1 = yv.y + hv.y, v2 = yv.z + hv.z, v3 = yv.w + hv.w;
    float s = v0 + v1 + v2 + v3;
#pragma unroll
    for (int o = 16; o; o >>= 1) s += __shfl_xor_sync(0xFFFFFFFFu, s, o);
    float mu = s * (1.0f / D_DIM);
    float d0 = v0 - mu, d1 = v1 - mu, d2 = v2 - mu, d3 = v3 - mu;
    float q = d0 * d0 + d1 * d1 + d2 * d2 + d3 * d3;
#pragma unroll
    for (int o = 16; o; o >>= 1) q += __shfl_xor_sync(0xFFFFFFFFu, q, o);
    float rs = rsqrtf(q * (1.0f / D_DIM) + LN_EPS);
    float4 gv = *reinterpret_cast<const float4*>(&gamma[lane << 2]);
    float4 bv = *reinterpret_cast<const float4*>(&beta[lane << 2]);
    float4 o4;
    o4.x = d0 * rs * gv.x + bv.x;
    o4.y = d1 * rs * gv.y + bv.y;
    o4.z = d2 * rs * gv.z + bv.z;
    o4.w = d3 * rs * gv.w + bv.w;
    *reinterpret_cast<float4*>(&out[base]) = o4;
}

// ---------------- launch ----------------
extern "C" void kernel_launch(void* const* d_in, const int* in_sizes, int n_in,
                              void* d_out, int out_size) {
    const float* s       = (const float*)d_in[0];
    const float* c       = (const float*)d_in[1];
    const int*   src_idx = (const int*)d_in[2];
    const int*   dst_idx = (const int*)d_in[3];
    const float* W_fc    = (const float*)d_in[4];
    const float* a_attn  = (const float*)d_in[5];
    const float* w1      = (const float*)d_in[6];
    const float* b1      = (const float*)d_in[7];
    const float* w2      = (const float*)d_in[8];
    const float* b2      = (const float*)d_in[9];
    const float* ln_g    = (const float*)d_in[10];
    const float* ln_b    = (const float*)d_in[11];
    float* out = (float*)d_out;

    int Ns = in_sizes[0] / D_DIM;
    int Nc = in_sizes[1] / D_DIM;
    int E  = in_sizes[2];

    float *z, *zs, *hc, *y; int* sg;
    __nv_bfloat16 *sh, *sl, *hch, *hcl, *th, *tl, *wfch, *wfcl, *w1h, *w1l, *w2h, *w2l;
    cudaGetSymbolAddress((void**)&z,   g_z);
    cudaGetSymbolAddress((void**)&zs,  g_zs);
    cudaGetSymbolAddress((void**)&sg,  g_seg);
    cudaGetSymbolAddress((void**)&hc,  g_hc);
    cudaGetSymbolAddress((void**)&y,   g_y);
    cudaGetSymbolAddress((void**)&sh,  g_s_h);  cudaGetSymbolAddress((void**)&sl,  g_s_l);
    cudaGetSymbolAddress((void**)&hch, g_hc_h); cudaGetSymbolAddress((void**)&hcl, g_hc_l);
    cudaGetSymbolAddress((void**)&th,  g_t_h);  cudaGetSymbolAddress((void**)&tl,  g_t_l);
    cudaGetSymbolAddress((void**)&wfch, g_wfc_h); cudaGetSymbolAddress((void**)&wfcl, g_wfc_l);
    cudaGetSymbolAddress((void**)&w1h, g_w1_h); cudaGetSymbolAddress((void**)&w1l, g_w1_l);
    cudaGetSymbolAddress((void**)&w2h, g_w2_h); cudaGetSymbolAddress((void**)&w2l, g_w2_l);

    cudaFuncSetAttribute(mma_gemm<0>, cudaFuncAttributeMaxDynamicSharedMemorySize, MM_SMEM_BYTES);
    cudaFuncSetAttribute(mma_gemm<1>, cudaFuncAttributeMaxDynamicSharedMemorySize, MM_SMEM_BYTES);
    cudaFuncSetAttribute(mma_gemm<2>, cudaFuncAttributeMaxDynamicSharedMemorySize, MM_SMEM_BYTES);

    // 0) split inputs to bf16 hi/lo
    split_kernel<<<(Ns * D_DIM + 255) / 256, 256>>>(s, sh, sl, Ns * D_DIM);
    split_kernel<<<(D_DIM * D_DIM + 255) / 256, 256>>>(W_fc, wfch, wfcl, D_DIM * D_DIM);
    split_kernel<<<(H_DIM * D_DIM + 255) / 256, 256>>>(w1, w1h, w1l, H_DIM * D_DIM);
    split_kernel<<<(D_DIM * H_DIM + 255) / 256, 256>>>(w2, w2h, w2l, D_DIM * H_DIM);

    int gy = (Ns + 127) / 128;     // == (Nc + 127) / 128, Ns == Nc
    // 1) z = s @ W_fc^T   [Ns,128]
    {
        dim3 grid(D_DIM / 64, gy);
        mma_gemm<0><<<grid, 256, MM_SMEM_BYTES>>>(sh, sl, wfch, wfcl, nullptr,
                                                  z, nullptr, nullptr, Ns, D_DIM, D_DIM);
    }
    // 2) zs = z @ a_attn[:128]
    zs_kernel<<<(Ns * 32 + 255) / 256, 256>>>(z, a_attn, zs, Ns);
    // 3) segment starts
    segstart_kernel<<<(E + 255) / 256, 256>>>(dst_idx, sg, E, Nc);
    // 4) fused softmax + aggregate + elu + residual (+ hi/lo split of hc)
    agg_kernel<<<(Nc * 32 + 255) / 256, 256>>>(z, zs, src_idx, sg, c, hc, hch, hcl, Nc);
    // 5) t = relu(hc @ w1^T + b1) -> split bf16  [Nc,512]
    {
        dim3 grid(H_DIM / 64, gy);
        mma_gemm<1><<<grid, 256, MM_SMEM_BYTES>>>(hch, hcl, w1h, w1l, b1,
                                                  nullptr, th, tl, Nc, H_DIM, D_DIM);
    }
    // 6) y = t @ w2^T + b2   [Nc,128]
    {
        dim3 grid(D_DIM / 64, gy);
        mma_gemm<2><<<grid, 256, MM_SMEM_BYTES>>>(th, tl, w2h, w2l, b2,
                                                  y, nullptr, nullptr, Nc, D_DIM, H_DIM);
    }
    // 7) out = LN(y + hc)
    ln_kernel<<<(Nc * 32 + 255) / 256, 256>>>(y, hc, ln_g, ln_b, out, Nc);
}